// round 6
// baseline (speedup 1.0000x reference)
#include <cuda_runtime.h>
#include <cuda_bf16.h>
#include <math.h>
#include <stdint.h>

// ---------------------------------------------------------------------------
// SupConLossWithPrototype via int8 IMMA (m16n8k32.s8, s32 accumulate).
//   Per-row symmetric quantization, exact dequant acc*ra_i*rb_j.
//   E[i] = sum_{j novel} exp(f_i . f_j / T), fused ex2 row-reduce.
// ---------------------------------------------------------------------------

#define MAXM 8192
#define NCHUNK 7
#define LOG2E5 7.2134752044448170f

__device__ __align__(16) int8_t d_A8[(size_t)MAXM * 128];
__device__ __align__(16) int8_t d_B8[(size_t)(MAXM + 128) * 128];
__device__ float d_ascale[MAXM];
__device__ float d_bscale[MAXM + 128];
__device__ int   d_pos[MAXM];
__device__ int   d_flag[MAXM];
__device__ int   d_Nn;
__device__ float d_gpart[(size_t)1024 * 128];
__device__ float d_g[128];
__device__ float d_Epart[(size_t)NCHUNK * MAXM];
__device__ float d_rowloss[MAXM];

// ------------------------------ helpers ------------------------------------

__device__ __forceinline__ uint32_t s2u(const void* p) {
    uint32_t a;
    asm("{ .reg .u64 t; cvta.to.shared.u64 t, %1; cvt.u32.u64 %0, t; }"
        : "=r"(a) : "l"(p));
    return a;
}

__device__ __forceinline__ void cp16(uint32_t s, const void* g) {
    asm volatile("cp.async.cg.shared.global [%0], [%1], 16;" :: "r"(s), "l"(g));
}
#define CP_COMMIT() asm volatile("cp.async.commit_group;" ::: "memory")

__device__ __forceinline__ void ldsm4(uint32_t (&r)[4], uint32_t addr) {
    asm volatile("ldmatrix.sync.aligned.m8n8.x4.shared.b16 {%0,%1,%2,%3}, [%4];"
                 : "=r"(r[0]), "=r"(r[1]), "=r"(r[2]), "=r"(r[3]) : "r"(addr));
}

__device__ __forceinline__ void mma16832(int (&d)[4], const uint32_t (&a)[4],
                                         uint32_t b0, uint32_t b1) {
    asm volatile(
        "mma.sync.aligned.m16n8k32.row.col.s32.s8.s8.s32 "
        "{%0,%1,%2,%3}, {%4,%5,%6,%7}, {%8,%9}, {%0,%1,%2,%3};"
        : "+r"(d[0]), "+r"(d[1]), "+r"(d[2]), "+r"(d[3])
        : "r"(a[0]), "r"(a[1]), "r"(a[2]), "r"(a[3]), "r"(b0), "r"(b1));
}

// XOR-swizzled smem tile: 128 rows x 128B row (8 x 16B chunks).
__device__ __forceinline__ uint32_t swz8(uint32_t base, int row, int kc) {
    return base + row * 128 + (((uint32_t)(kc ^ (row & 7))) << 4);
}

__device__ __forceinline__ float ex2f(float t) {
    float r;
    asm("ex2.approx.f32 %0, %1;" : "=f"(r) : "f"(t));
    return r;
}

// exp on the FMA pipe (finalize only), rel err ~1.5e-7.
__device__ __forceinline__ float fexp(float x) {
    float t = x * 1.4426950408889634f;
    float z = t + 12582912.0f;
    int   ki = __float_as_int(z) - 0x4B400000;
    float r = t - (z - 12582912.0f);
    float p =      1.5403530393381610e-4f;
    p = fmaf(p, r, 1.3333558146428443e-3f);
    p = fmaf(p, r, 9.6181291076284772e-3f);
    p = fmaf(p, r, 5.5504108664821580e-2f);
    p = fmaf(p, r, 2.4022650695910072e-1f);
    p = fmaf(p, r, 6.9314718055994531e-1f);
    p = fmaf(p, r, 1.0f);
    return __int_as_float(__float_as_int(p) + (ki << 23));
}

// --------------------------- setup kernels --------------------------------

__global__ void scan_flags_kernel(const int* __restrict__ labels,
                                  const int* __restrict__ plab, int M, int B) {
    __shared__ int sPL[128];
    __shared__ int sWarp[32];
    __shared__ int sBase, sTot;
    int tid = threadIdx.x, lane = tid & 31, wid = tid >> 5;
    if (tid < B) sPL[tid] = plab[tid];
    if (tid == 0) sBase = 0;
    __syncthreads();
    for (int c0 = 0; c0 < M; c0 += 1024) {
        int i = c0 + tid;
        int f = 0;
        if (i < M) {
            int lab = labels[i];
            int hit = 0;
            for (int b = 0; b < B; ++b) hit |= (lab == sPL[b]);
            f = hit ^ 1;
            d_flag[i] = f;
        }
        unsigned bal = __ballot_sync(0xffffffffu, f != 0);
        int lanePre = __popc(bal & ((1u << lane) - 1u));
        if (lane == 0) sWarp[wid] = __popc(bal);
        __syncthreads();
        if (wid == 0) {
            int v = sWarp[lane];
            int pre = v;
            #pragma unroll
            for (int off = 1; off < 32; off <<= 1) {
                int n = __shfl_up_sync(0xffffffffu, pre, off);
                if (lane >= off) pre += n;
            }
            sWarp[lane] = pre - v;
            if (lane == 31) sTot = pre;
        }
        __syncthreads();
        if (i < M && f) d_pos[i] = sBase + sWarp[wid] + lanePre;
        __syncthreads();
        if (tid == 0) sBase += sTot;
        __syncthreads();
    }
    if (tid == 0) d_Nn = sBase;
}

// Per-row symmetric int8 quantization + novel-row compaction + g partials.
// One warp per row, 8 rows per CTA.
__global__ void quant_kernel(const float* __restrict__ F, int M) {
    __shared__ float sg[8][128];
    int tid = threadIdx.x, lane = tid & 31, w = tid >> 5;
    int r = blockIdx.x * 8 + w;

    float4 v = *(const float4*)(F + (size_t)r * 128 + lane * 4);
    float m = fmaxf(fmaxf(fabsf(v.x), fabsf(v.y)),
                    fmaxf(fabsf(v.z), fabsf(v.w)));
    #pragma unroll
    for (int off = 16; off; off >>= 1)
        m = fmaxf(m, __shfl_xor_sync(0xffffffffu, m, off));
    float sc = 127.0f / m;
    int q0 = __float2int_rn(v.x * sc);
    int q1 = __float2int_rn(v.y * sc);
    int q2 = __float2int_rn(v.z * sc);
    int q3 = __float2int_rn(v.w * sc);
    uint32_t pk = (q0 & 255) | ((q1 & 255) << 8) |
                  ((q2 & 255) << 16) | ((q3 & 255) << 24);
    ((uint32_t*)d_A8)[(size_t)r * 32 + lane] = pk;

    int fl = d_flag[r];
    if (fl) {
        int pos = d_pos[r];
        ((uint32_t*)d_B8)[(size_t)pos * 32 + lane] = pk;
        if (lane == 0) d_bscale[pos] = m * (1.0f / 127.0f);
    }
    if (lane == 0) d_ascale[r] = m * (1.0f / 127.0f);

    float ff = (float)fl;
    sg[w][lane * 4 + 0] = v.x * ff;
    sg[w][lane * 4 + 1] = v.y * ff;
    sg[w][lane * 4 + 2] = v.z * ff;
    sg[w][lane * 4 + 3] = v.w * ff;
    __syncthreads();
    if (tid < 128) {
        float s = 0.f;
        #pragma unroll
        for (int q = 0; q < 8; ++q) s += sg[q][tid];
        d_gpart[(size_t)blockIdx.x * 128 + tid] = s;
    }
}

// Final g reduce + zero-pad the last B tile (rows Nn..Npad).
__global__ void gred_kernel(int nb) {          // nb = 1024, block = 1024
    __shared__ float sm[1024];
    int t = threadIdx.x;
    int k = t & 127, p = t >> 7;
    float s = 0.f;
    for (int b = p; b < nb; b += 8) s += d_gpart[(size_t)b * 128 + k];
    sm[t] = s;
    __syncthreads();
    if (p == 0) {
        float tot = sm[k];
        #pragma unroll
        for (int q = 1; q < 8; ++q) tot += sm[q * 128 + k];
        d_g[k] = tot;
    }
    int Nn = d_Nn;
    int Npad = (Nn + 127) & ~127;
    for (int idx = t; idx < (Npad - Nn) * 32; idx += 1024) {
        int row = Nn + (idx >> 5), wd = idx & 31;
        ((uint32_t*)d_B8)[(size_t)row * 32 + wd] = 0;
    }
    for (int idx = Nn + t; idx < Npad; idx += 1024) d_bscale[idx] = 0.f;
}

// ---------------------- main IMMA exp-sum kernel ---------------------------
// CTA: 128 rows x stream of 128-col novel tiles (stride NCHUNK).
// 512 threads, 16 warps in 4x4 grid, warp tile 32x32, m16n8k32.s8.
// smem: A 16KB + B double 32KB + scales ~1.5KB.

#define OFF_A    0
#define OFF_B0   16384
#define OFF_B1   32768
#define OFF_ASC  49152
#define OFF_BSC0 49664
#define OFF_BSC1 50176
#define SMEM_MAIN (50688 + 1024)

__global__ __launch_bounds__(512, 1) void mma_expsum_kernel(int M) {
    extern __shared__ char dyn[];
    char* alg = (char*)(((uintptr_t)dyn + 1023) & ~(uintptr_t)1023);
    const uint32_t sbase = s2u(alg);
    const uint32_t sA = sbase + OFF_A;
    const uint32_t sB[2] = {sbase + OFF_B0, sbase + OFF_B1};
    const float* pAsc = (const float*)(alg + OFF_ASC);
    const float* pBsc[2] = {(const float*)(alg + OFF_BSC0),
                            (const float*)(alg + OFF_BSC1)};

    int tid = threadIdx.x;
    int lane = tid & 31, w = tid >> 5;
    int wr = w >> 2, wc = w & 3;               // warp grid 4 x 4
    int g4 = lane >> 2;
    int rowbase = blockIdx.x * 128;
    int chunk = blockIdx.y;
    int Nn = d_Nn;
    int ntiles = (Nn + 127) >> 7;
    int nt = (ntiles > chunk) ? ((ntiles - chunk + NCHUNK - 1) / NCHUNK) : 0;

    // Prologue: A + A-scales + B0 + B0-scales (group 0); B1 (group 1).
    {
        const char* ga = (const char*)d_A8 + (size_t)blockIdx.x * 16384;
        #pragma unroll
        for (int it = 0; it < 2; ++it) {
            int c = it * 512 + tid;
            cp16(swz8(sA, c >> 3, c & 7), ga + (size_t)c * 16);
        }
        if (tid < 32)
            cp16(sbase + OFF_ASC + tid * 16,
                 (const char*)d_ascale + (size_t)blockIdx.x * 512 + tid * 16);
        if (nt > 0) {
            const char* gb = (const char*)d_B8 + (size_t)chunk * 16384;
            #pragma unroll
            for (int it = 0; it < 2; ++it) {
                int c = it * 512 + tid;
                cp16(swz8(sB[0], c >> 3, c & 7), gb + (size_t)c * 16);
            }
            if (tid < 32)
                cp16(sbase + OFF_BSC0 + tid * 16,
                     (const char*)d_bscale + (size_t)chunk * 512 + tid * 16);
        }
        CP_COMMIT();
        if (nt > 1) {
            const char* gb = (const char*)d_B8 +
                             (size_t)(chunk + NCHUNK) * 16384;
            #pragma unroll
            for (int it = 0; it < 2; ++it) {
                int c = it * 512 + tid;
                cp16(swz8(sB[1], c >> 3, c & 7), gb + (size_t)c * 16);
            }
            if (tid < 32)
                cp16(sbase + OFF_BSC1 + tid * 16,
                     (const char*)d_bscale + (size_t)(chunk + NCHUNK) * 512 + tid * 16);
            CP_COMMIT();
        }
    }

    int rl = lane & 15;
    int khalf = lane >> 4;
    float rs[4];
    #pragma unroll
    for (int q = 0; q < 4; ++q) rs[q] = 0.f;

    for (int k = 0; k < nt; ++k) {
        int p = k & 1;
        if (k + 1 < nt) asm volatile("cp.async.wait_group 1;" ::: "memory");
        else            asm volatile("cp.async.wait_group 0;" ::: "memory");
        __syncthreads();

        int acc[2][4][4];
        #pragma unroll
        for (int mi = 0; mi < 2; ++mi)
            #pragma unroll
            for (int ni = 0; ni < 4; ++ni)
                #pragma unroll
                for (int q = 0; q < 4; ++q) acc[mi][ni][q] = 0;

        #pragma unroll
        for (int ks = 0; ks < 4; ++ks) {
            int kc = ks * 2 + khalf;
            uint32_t a[2][4], b[2][4];
            #pragma unroll
            for (int mi = 0; mi < 2; ++mi)
                ldsm4(a[mi], swz8(sA, wr * 32 + mi * 16 + rl, kc));
            #pragma unroll
            for (int n2 = 0; n2 < 2; ++n2)
                ldsm4(b[n2], swz8(sB[p], wc * 32 + n2 * 16 + rl, kc));
            #pragma unroll
            for (int mi = 0; mi < 2; ++mi)
                #pragma unroll
                for (int ni = 0; ni < 4; ++ni) {
                    int n2 = ni >> 1, pr = ni & 1;
                    mma16832(acc[mi][ni], a[mi], b[n2][pr], b[n2][pr + 2]);
                }
        }
        __syncthreads();

        if (k + 2 < nt) {                   // prefetch B(k+2) into buffer p
            const char* gb = (const char*)d_B8 +
                             (size_t)(chunk + (k + 2) * NCHUNK) * 16384;
            #pragma unroll
            for (int it = 0; it < 2; ++it) {
                int c = it * 512 + tid;
                cp16(swz8(sB[p], c >> 3, c & 7), gb + (size_t)c * 16);
            }
            if (tid < 32)
                cp16(sbase + (p ? OFF_BSC1 : OFF_BSC0) + tid * 16,
                     (const char*)d_bscale +
                     (size_t)(chunk + (k + 2) * NCHUNK) * 512 + tid * 16);
            CP_COMMIT();
        }

        // Dequant + exp + row accumulate.
        float ra5[4];
        #pragma unroll
        for (int j = 0; j < 4; ++j)
            ra5[j] = pAsc[wr * 32 + j * 8 + g4] * LOG2E5;
        float rb[8];
        #pragma unroll
        for (int ni = 0; ni < 4; ++ni) {
            rb[ni * 2 + 0] = pBsc[p][wc * 32 + ni * 8 + (lane & 3) * 2 + 0];
            rb[ni * 2 + 1] = pBsc[p][wc * 32 + ni * 8 + (lane & 3) * 2 + 1];
        }
        int cwarp = (chunk + k * NCHUNK) * 128 + wc * 32;
        if (cwarp + 32 <= Nn) {
            #pragma unroll
            for (int mi = 0; mi < 2; ++mi)
                #pragma unroll
                for (int ni = 0; ni < 4; ++ni) {
                    rs[mi * 2 + 0] +=
                        ex2f((float)acc[mi][ni][0] * (ra5[mi * 2 + 0] * rb[ni * 2 + 0])) +
                        ex2f((float)acc[mi][ni][1] * (ra5[mi * 2 + 0] * rb[ni * 2 + 1]));
                    rs[mi * 2 + 1] +=
                        ex2f((float)acc[mi][ni][2] * (ra5[mi * 2 + 1] * rb[ni * 2 + 0])) +
                        ex2f((float)acc[mi][ni][3] * (ra5[mi * 2 + 1] * rb[ni * 2 + 1]));
                }
        } else {
            #pragma unroll
            for (int mi = 0; mi < 2; ++mi)
                #pragma unroll
                for (int ni = 0; ni < 4; ++ni) {
                    int c0 = cwarp + ni * 8 + (lane & 3) * 2;
                    float t0 = (c0     < Nn) ? (float)acc[mi][ni][0] * (ra5[mi*2+0] * rb[ni*2+0]) : -1e30f;
                    float t1 = (c0 + 1 < Nn) ? (float)acc[mi][ni][1] * (ra5[mi*2+0] * rb[ni*2+1]) : -1e30f;
                    float t2 = (c0     < Nn) ? (float)acc[mi][ni][2] * (ra5[mi*2+1] * rb[ni*2+0]) : -1e30f;
                    float t3 = (c0 + 1 < Nn) ? (float)acc[mi][ni][3] * (ra5[mi*2+1] * rb[ni*2+1]) : -1e30f;
                    rs[mi * 2 + 0] += ex2f(t0) + ex2f(t1);
                    rs[mi * 2 + 1] += ex2f(t2) + ex2f(t3);
                }
        }
    }

    asm volatile("cp.async.wait_group 0;" ::: "memory");

    // Quad reduce (lanes sharing a row), then cross-warp-col reduce in smem.
    #pragma unroll
    for (int q = 0; q < 4; ++q) {
        rs[q] += __shfl_xor_sync(0xffffffffu, rs[q], 1);
        rs[q] += __shfl_xor_sync(0xffffffffu, rs[q], 2);
    }
    __syncthreads();
    float* sred = (float*)alg;              // 128 rows x 4 warp-cols
    if ((lane & 3) == 0) {
        #pragma unroll
        for (int j = 0; j < 4; ++j) {
            int row = wr * 32 + j * 8 + g4;
            sred[row * 4 + wc] = rs[j];
        }
    }
    __syncthreads();
    if (tid < 128) {
        float s = sred[tid * 4] + sred[tid * 4 + 1] +
                  sred[tid * 4 + 2] + sred[tid * 4 + 3];
        d_Epart[(size_t)chunk * M + rowbase + tid] = s;
    }
}

// --------------------------- finalize + reduce -----------------------------

__global__ void finalize_kernel(const float* __restrict__ F,
                                const float* __restrict__ protos,
                                const int* __restrict__ labels,
                                int M, int B) {
    extern __shared__ float sP[];          // B*129 floats
    __shared__ float fR[8][128];
    int tid = threadIdx.x, lane = tid & 31, w = tid >> 5;

    for (int idx = tid; idx < B * 128; idx += 256) {
        int b = idx >> 7, k = idx & 127;
        sP[b * 129 + k] = protos[idx];
    }
    int i = blockIdx.x * 8 + w;
    {
        float4 v = *(const float4*)(F + (size_t)i * 128 + lane * 4);
        *(float4*)&fR[w][lane * 4] = v;
    }
    __syncthreads();

    float dg = 0.f, ds = 0.f;
    #pragma unroll
    for (int q = 0; q < 4; ++q) {
        float fv = fR[w][lane * 4 + q];
        dg = fmaf(fv, d_g[lane * 4 + q], dg);
        ds = fmaf(fv, fv, ds);
    }

    float psum = 0.f, pexp = 0.f, bipi = 0.f;
    int lab = labels[i];
    #pragma unroll
    for (int pb = 0; pb < 4; ++pb) {
        int b = lane + pb * 32;
        if (b < B) {
            float d = 0.f;
            #pragma unroll 8
            for (int k = 0; k < 128; ++k)
                d = fmaf(fR[w][k], sP[b * 129 + k], d);
            float P = d * 5.0f;
            psum += P;
            pexp += fexp(P);
            if (b == lab) bipi = P;
        }
    }
    #pragma unroll
    for (int off = 16; off; off >>= 1) {
        dg   += __shfl_xor_sync(0xffffffffu, dg, off);
        ds   += __shfl_xor_sync(0xffffffffu, ds, off);
        psum += __shfl_xor_sync(0xffffffffu, psum, off);
        pexp += __shfl_xor_sync(0xffffffffu, pexp, off);
        bipi += __shfl_xor_sync(0xffffffffu, bipi, off);
    }

    if (lane == 0) {
        float E = 0.f;
        #pragma unroll
        for (int c = 0; c < NCHUNK; ++c) E += d_Epart[(size_t)c * M + i];
        float loss;
        if (d_flag[i]) {
            float Sii = ds * 5.0f;
            float den = (E - fexp(Sii)) + psum;
            int cnt = d_Nn - 1;
            if (cnt > 0) {
                float sumS = dg * 5.0f - Sii;
                loss = -((sumS - logf(den) * (float)cnt) / (float)cnt);
            } else {
                loss = 0.f;
            }
        } else {
            loss = -(bipi - logf(E + pexp));
        }
        d_rowloss[i] = loss;
    }
}

__global__ void reduce_kernel(float* __restrict__ out, int M) {
    __shared__ float sm[1024];
    int tid = threadIdx.x;
    float s = 0.f;
    for (int i = tid; i < M; i += 1024) s += d_rowloss[i];
    sm[tid] = s;
    __syncthreads();
    for (int off = 512; off; off >>= 1) {
        if (tid < off) sm[tid] += sm[tid + off];
        __syncthreads();
    }
    if (tid == 0) out[0] = sm[0] / (float)M;
}

// ------------------------------- launcher ----------------------------------

extern "C" void kernel_launch(void* const* d_in, const int* in_sizes, int n_in,
                              void* d_out, int out_size) {
    const float* F      = (const float*)d_in[0];
    const int*   labels = (const int*)d_in[1];
    const float* protos = (const float*)d_in[2];
    const int*   plab   = (const int*)d_in[3];
    int M = in_sizes[1];                  // 8192
    int B = in_sizes[3];                  // 100

    scan_flags_kernel<<<1, 1024>>>(labels, plab, M, B);
    quant_kernel<<<M / 8, 256>>>(F, M);
    gred_kernel<<<1, 1024>>>(M / 8);

    cudaFuncSetAttribute(mma_expsum_kernel,
                         cudaFuncAttributeMaxDynamicSharedMemorySize,
                         SMEM_MAIN);
    mma_expsum_kernel<<<dim3(M / 128, NCHUNK), 512, SMEM_MAIN>>>(M);

    size_t smemP = (size_t)B * 129 * sizeof(float);
    cudaFuncSetAttribute(finalize_kernel,
                         cudaFuncAttributeMaxDynamicSharedMemorySize,
                         (int)smemP);
    finalize_kernel<<<M / 8, 256, smemP>>>(F, protos, labels, M, B);

    reduce_kernel<<<1, 1024>>>((float*)d_out, M);
}

// round 7
// speedup vs baseline: 1.5437x; 1.5437x over previous
#include <cuda_runtime.h>
#include <cuda_bf16.h>
#include <math.h>
#include <stdint.h>

// ---------------------------------------------------------------------------
// SupConLossWithPrototype via mma.sync bf16, MUFU exp epilogue.
//   E[i] = sum_{j novel} exp(f_i . f_j / T).
//   2 CTAs/SM for tensor-pipe overlap; slim setup path.
// ---------------------------------------------------------------------------

#define MAXM 8192
#define NCHUNK 9
#define LOG2E5 7.2134752044448170f

__device__ __align__(16) __nv_bfloat16 d_Ahi[(size_t)MAXM * 128];
__device__ __align__(16) __nv_bfloat16 d_Bhi[(size_t)(MAXM + 128) * 128];
__device__ int   d_pos[MAXM];
__device__ int   d_flag[MAXM];
__device__ int   d_Nn;
__device__ float d_gpart[512 * 128];
__device__ float d_g[128];
__device__ float d_Epart[(size_t)NCHUNK * MAXM];
__device__ float d_rowloss[MAXM];

// ------------------------------ helpers ------------------------------------

__device__ __forceinline__ uint32_t s2u(const void* p) {
    uint32_t a;
    asm("{ .reg .u64 t; cvta.to.shared.u64 t, %1; cvt.u32.u64 %0, t; }"
        : "=r"(a) : "l"(p));
    return a;
}

__device__ __forceinline__ void cp16(uint32_t s, const void* g) {
    asm volatile("cp.async.cg.shared.global [%0], [%1], 16;" :: "r"(s), "l"(g));
}
#define CP_COMMIT() asm volatile("cp.async.commit_group;" ::: "memory")

__device__ __forceinline__ void ldsm4(uint32_t (&r)[4], uint32_t addr) {
    asm volatile("ldmatrix.sync.aligned.m8n8.x4.shared.b16 {%0,%1,%2,%3}, [%4];"
                 : "=r"(r[0]), "=r"(r[1]), "=r"(r[2]), "=r"(r[3]) : "r"(addr));
}

__device__ __forceinline__ void mma16816(float (&d)[4], const uint32_t (&a)[4],
                                         uint32_t b0, uint32_t b1) {
    asm volatile(
        "mma.sync.aligned.m16n8k16.row.col.f32.bf16.bf16.f32 "
        "{%0,%1,%2,%3}, {%4,%5,%6,%7}, {%8,%9}, {%0,%1,%2,%3};"
        : "+f"(d[0]), "+f"(d[1]), "+f"(d[2]), "+f"(d[3])
        : "r"(a[0]), "r"(a[1]), "r"(a[2]), "r"(a[3]), "r"(b0), "r"(b1));
}

// XOR-swizzled smem tile: 128 rows x 256B row (16 x 16B chunks).
__device__ __forceinline__ uint32_t swz(uint32_t base, int row, int kchunk) {
    return base + row * 256 + (((uint32_t)(kchunk ^ (row & 7))) << 4);
}

__device__ __forceinline__ float ex2f(float t) {
    float r;
    asm("ex2.approx.f32 %0, %1;" : "=f"(r) : "f"(t));
    return r;
}

// exp on the FMA pipe (finalize only), rel err ~1.5e-7.
__device__ __forceinline__ float fexp(float x) {
    float t = x * 1.4426950408889634f;
    float z = t + 12582912.0f;
    int   ki = __float_as_int(z) - 0x4B400000;
    float r = t - (z - 12582912.0f);
    float p =      1.5403530393381610e-4f;
    p = fmaf(p, r, 1.3333558146428443e-3f);
    p = fmaf(p, r, 9.6181291076284772e-3f);
    p = fmaf(p, r, 5.5504108664821580e-2f);
    p = fmaf(p, r, 2.4022650695910072e-1f);
    p = fmaf(p, r, 6.9314718055994531e-1f);
    p = fmaf(p, r, 1.0f);
    return __int_as_float(__float_as_int(p) + (ki << 23));
}

// --------------------------- setup kernels --------------------------------

__global__ void scan_flags_kernel(const int* __restrict__ labels,
                                  const int* __restrict__ plab, int M, int B) {
    __shared__ int sPL[128];
    __shared__ int sWarp[32];
    __shared__ int sBase, sTot;
    int tid = threadIdx.x, lane = tid & 31, wid = tid >> 5;
    if (tid < B) sPL[tid] = plab[tid];
    if (tid == 0) sBase = 0;
    __syncthreads();
    for (int c0 = 0; c0 < M; c0 += 1024) {
        int i = c0 + tid;
        int f = 0;
        if (i < M) {
            int lab = labels[i];
            int hit = 0;
            for (int b = 0; b < B; ++b) hit |= (lab == sPL[b]);
            f = hit ^ 1;
            d_flag[i] = f;
        }
        unsigned bal = __ballot_sync(0xffffffffu, f != 0);
        int lanePre = __popc(bal & ((1u << lane) - 1u));
        if (lane == 0) sWarp[wid] = __popc(bal);
        __syncthreads();
        if (wid == 0) {
            int v = sWarp[lane];
            int pre = v;
            #pragma unroll
            for (int off = 1; off < 32; off <<= 1) {
                int n = __shfl_up_sync(0xffffffffu, pre, off);
                if (lane >= off) pre += n;
            }
            sWarp[lane] = pre - v;
            if (lane == 31) sTot = pre;
        }
        __syncthreads();
        if (i < M && f) d_pos[i] = sBase + sWarp[wid] + lanePre;
        __syncthreads();
        if (tid == 0) sBase += sTot;
        __syncthreads();
    }
    if (tid == 0) d_Nn = sBase;
}

// bf16 convert + novel compaction + per-block g partials (single F read).
// 256 threads = 16 rows x 16 col-chunks of 8.
__global__ void convert_kernel(const float* __restrict__ F, int M) {
    __shared__ float sg[16][128];
    int tid = threadIdx.x;
    int idx = blockIdx.x * 256 + tid;
    int r = idx >> 4, kc = idx & 15, lr = tid >> 4;

    float4 v0 = *(const float4*)(F + (size_t)r * 128 + kc * 8);
    float4 v1 = *(const float4*)(F + (size_t)r * 128 + kc * 8 + 4);
    float av[8] = {v0.x, v0.y, v0.z, v0.w, v1.x, v1.y, v1.z, v1.w};
    union { __nv_bfloat16 h[8]; uint4 u; } ph;
    #pragma unroll
    for (int q = 0; q < 8; ++q) ph.h[q] = __float2bfloat16(av[q]);
    ((uint4*)d_Ahi)[(size_t)r * 16 + kc] = ph.u;
    int fl = d_flag[r];
    if (fl)
        ((uint4*)d_Bhi)[(size_t)d_pos[r] * 16 + kc] = ph.u;

    float ff = (float)fl;
    #pragma unroll
    for (int q = 0; q < 8; ++q) sg[lr][kc * 8 + q] = av[q] * ff;
    __syncthreads();
    if (tid < 128) {
        float s = 0.f;
        #pragma unroll
        for (int q = 0; q < 16; ++q) s += sg[q][tid];
        d_gpart[blockIdx.x * 128 + tid] = s;
    }
}

// Final g reduce + zero-pad last B tile rows (Nn..Npad).
__global__ void gred_kernel(int nb) {          // nb = 512, block = 1024
    __shared__ float sm[1024];
    int t = threadIdx.x;
    int k = t & 127, p = t >> 7;
    float s = 0.f;
    for (int b = p; b < nb; b += 8) s += d_gpart[b * 128 + k];
    sm[t] = s;
    __syncthreads();
    if (p == 0) {
        float tot = sm[k];
        #pragma unroll
        for (int q = 1; q < 8; ++q) tot += sm[q * 128 + k];
        d_g[k] = tot;
    }
    int Nn = d_Nn;
    int Npad = (Nn + 127) & ~127;
    for (int idx = t; idx < (Npad - Nn) * 16; idx += 1024) {
        int row = Nn + (idx >> 4), kc = idx & 15;
        ((uint4*)d_Bhi)[(size_t)row * 16 + kc] = make_uint4(0, 0, 0, 0);
    }
}

// ---------------------- main mma.sync exp-sum kernel -----------------------
// CTA: 128 rows x stream of 128-col novel tiles (stride NCHUNK).
// smem: A resident (32KB) + B double buffer (64KB) = 96KB; 2 CTAs/SM.
// 8 warps in 2x4 grid, warp tile 64x32, bf16 mma, MUFU exp.

__global__ __launch_bounds__(256, 2) void mma_expsum_kernel(int M) {
    extern __shared__ char dyn[];
    const uint32_t sbase = s2u(dyn);
    const uint32_t sA = sbase;
    const uint32_t sB[2] = {sbase + 32768, sbase + 65536};

    int tid = threadIdx.x;
    int lane = tid & 31, w = tid >> 5;
    int wr = w >> 2, wc = w & 3;               // warp grid 2 x 4
    int rowbase = blockIdx.x * 128;
    int chunk = blockIdx.y;
    int Nn = d_Nn;
    int ntiles = (Nn + 127) >> 7;
    int nt = (ntiles > chunk) ? ((ntiles - chunk + NCHUNK - 1) / NCHUNK) : 0;

    // Prologue: A (group 0, with B0) + B1 (group 1).
    {
        const char* ga = (const char*)d_Ahi + (size_t)blockIdx.x * 32768;
        #pragma unroll
        for (int it = 0; it < 8; ++it) {
            int c = it * 256 + tid;
            cp16(swz(sA, c >> 4, c & 15), ga + (size_t)c * 16);
        }
        if (nt > 0) {
            const char* gb = (const char*)d_Bhi + (size_t)chunk * 32768;
            #pragma unroll
            for (int it = 0; it < 8; ++it) {
                int c = it * 256 + tid;
                cp16(swz(sB[0], c >> 4, c & 15), gb + (size_t)c * 16);
            }
        }
        CP_COMMIT();
        if (nt > 1) {
            const char* gb = (const char*)d_Bhi + (size_t)(chunk + NCHUNK) * 32768;
            #pragma unroll
            for (int it = 0; it < 8; ++it) {
                int c = it * 256 + tid;
                cp16(swz(sB[1], c >> 4, c & 15), gb + (size_t)c * 16);
            }
            CP_COMMIT();
        }
    }

    int rl = lane & 15;                 // ldmatrix row within 16-row group
    int khalf = lane >> 4;              // +1 k-chunk for upper half
    float rs[8];
    #pragma unroll
    for (int q = 0; q < 8; ++q) rs[q] = 0.f;

    for (int k = 0; k < nt; ++k) {
        int p = k & 1;
        if (k + 1 < nt) asm volatile("cp.async.wait_group 1;" ::: "memory");
        else            asm volatile("cp.async.wait_group 0;" ::: "memory");
        __syncthreads();

        float acc[4][4][4];
        #pragma unroll
        for (int mi = 0; mi < 4; ++mi)
            #pragma unroll
            for (int ni = 0; ni < 4; ++ni)
                #pragma unroll
                for (int q = 0; q < 4; ++q) acc[mi][ni][q] = 0.f;

        #pragma unroll
        for (int ks = 0; ks < 8; ++ks) {
            int kc = ks * 2 + khalf;
            uint32_t a[4][4], b[2][4];
            #pragma unroll
            for (int mi = 0; mi < 4; ++mi)
                ldsm4(a[mi], swz(sA, wr * 64 + mi * 16 + rl, kc));
            #pragma unroll
            for (int n2 = 0; n2 < 2; ++n2)
                ldsm4(b[n2], swz(sB[p], wc * 32 + n2 * 16 + rl, kc));
            #pragma unroll
            for (int mi = 0; mi < 4; ++mi)
                #pragma unroll
                for (int ni = 0; ni < 4; ++ni) {
                    int n2 = ni >> 1, pr = ni & 1;
                    mma16816(acc[mi][ni], a[mi], b[n2][pr], b[n2][pr + 2]);
                }
        }
        __syncthreads();

        if (k + 2 < nt) {                   // prefetch B(k+2) into buffer p
            const char* gb = (const char*)d_Bhi +
                             (size_t)(chunk + (k + 2) * NCHUNK) * 32768;
            #pragma unroll
            for (int it = 0; it < 8; ++it) {
                int c = it * 256 + tid;
                cp16(swz(sB[p], c >> 4, c & 15), gb + (size_t)c * 16);
            }
            CP_COMMIT();
        }

        // Fused exp + row accumulate (MUFU pipe).
        int cwarp = (chunk + k * NCHUNK) * 128 + wc * 32;
        if (cwarp + 32 <= Nn) {
            #pragma unroll
            for (int mi = 0; mi < 4; ++mi)
                #pragma unroll
                for (int ni = 0; ni < 4; ++ni) {
                    rs[mi * 2 + 0] += ex2f(acc[mi][ni][0] * LOG2E5) +
                                      ex2f(acc[mi][ni][1] * LOG2E5);
                    rs[mi * 2 + 1] += ex2f(acc[mi][ni][2] * LOG2E5) +
                                      ex2f(acc[mi][ni][3] * LOG2E5);
                }
        } else {
            #pragma unroll
            for (int mi = 0; mi < 4; ++mi)
                #pragma unroll
                for (int ni = 0; ni < 4; ++ni) {
                    int c0 = cwarp + ni * 8 + (lane & 3) * 2;
                    float t0 = (c0     < Nn) ? acc[mi][ni][0] * LOG2E5 : -1e30f;
                    float t1 = (c0 + 1 < Nn) ? acc[mi][ni][1] * LOG2E5 : -1e30f;
                    float t2 = (c0     < Nn) ? acc[mi][ni][2] * LOG2E5 : -1e30f;
                    float t3 = (c0 + 1 < Nn) ? acc[mi][ni][3] * LOG2E5 : -1e30f;
                    rs[mi * 2 + 0] += ex2f(t0) + ex2f(t1);
                    rs[mi * 2 + 1] += ex2f(t2) + ex2f(t3);
                }
        }
    }

    // Quad reduce (lanes sharing a row), then cross-warp-col reduce in smem.
    #pragma unroll
    for (int q = 0; q < 8; ++q) {
        rs[q] += __shfl_xor_sync(0xffffffffu, rs[q], 1);
        rs[q] += __shfl_xor_sync(0xffffffffu, rs[q], 2);
    }
    __syncthreads();
    float* sred = (float*)dyn;              // 128 rows x 4 warp-cols
    if ((lane & 3) == 0) {
        int g = lane >> 2;
        #pragma unroll
        for (int mi = 0; mi < 4; ++mi)
            #pragma unroll
            for (int r8 = 0; r8 < 2; ++r8) {
                int row = wr * 64 + mi * 16 + r8 * 8 + g;
                sred[row * 4 + wc] = rs[mi * 2 + r8];
            }
    }
    __syncthreads();
    if (tid < 128) {
        float s = sred[tid * 4] + sred[tid * 4 + 1] +
                  sred[tid * 4 + 2] + sred[tid * 4 + 3];
        d_Epart[(size_t)chunk * M + rowbase + tid] = s;
    }
}

// --------------------------- finalize + reduce -----------------------------
// 1024 threads, 32 rows per block (proto tile loaded once per 32 rows).

__global__ void finalize_kernel(const float* __restrict__ F,
                                const float* __restrict__ protos,
                                const int* __restrict__ labels,
                                int M, int B) {
    extern __shared__ float sP[];          // B*129 floats
    __shared__ float fR[32][128];
    int tid = threadIdx.x, lane = tid & 31, w = tid >> 5;

    for (int idx = tid; idx < B * 128; idx += 1024) {
        int b = idx >> 7, k = idx & 127;
        sP[b * 129 + k] = protos[idx];
    }
    int i = blockIdx.x * 32 + w;
    {
        float4 v = *(const float4*)(F + (size_t)i * 128 + lane * 4);
        *(float4*)&fR[w][lane * 4] = v;
    }
    __syncthreads();

    float dg = 0.f, ds = 0.f;
    #pragma unroll
    for (int q = 0; q < 4; ++q) {
        float fv = fR[w][lane * 4 + q];
        dg = fmaf(fv, d_g[lane * 4 + q], dg);
        ds = fmaf(fv, fv, ds);
    }

    float psum = 0.f, pexp = 0.f, bipi = 0.f;
    int lab = labels[i];
    #pragma unroll
    for (int pb = 0; pb < 4; ++pb) {
        int b = lane + pb * 32;
        if (b < B) {
            float d = 0.f;
            #pragma unroll 8
            for (int k = 0; k < 128; ++k)
                d = fmaf(fR[w][k], sP[b * 129 + k], d);
            float P = d * 5.0f;
            psum += P;
            pexp += fexp(P);
            if (b == lab) bipi = P;
        }
    }
    #pragma unroll
    for (int off = 16; off; off >>= 1) {
        dg   += __shfl_xor_sync(0xffffffffu, dg, off);
        ds   += __shfl_xor_sync(0xffffffffu, ds, off);
        psum += __shfl_xor_sync(0xffffffffu, psum, off);
        pexp += __shfl_xor_sync(0xffffffffu, pexp, off);
        bipi += __shfl_xor_sync(0xffffffffu, bipi, off);
    }

    if (lane == 0) {
        float E = 0.f;
        #pragma unroll
        for (int c = 0; c < NCHUNK; ++c) E += d_Epart[(size_t)c * M + i];
        float loss;
        if (d_flag[i]) {
            float Sii = ds * 5.0f;
            float den = (E - fexp(Sii)) + psum;
            int cnt = d_Nn - 1;
            if (cnt > 0) {
                float sumS = dg * 5.0f - Sii;
                loss = -((sumS - logf(den) * (float)cnt) / (float)cnt);
            } else {
                loss = 0.f;
            }
        } else {
            loss = -(bipi - logf(E + pexp));
        }
        d_rowloss[i] = loss;
    }
}

__global__ void reduce_kernel(float* __restrict__ out, int M) {
    __shared__ float sm[1024];
    int tid = threadIdx.x;
    float s = 0.f;
    for (int i = tid; i < M; i += 1024) s += d_rowloss[i];
    sm[tid] = s;
    __syncthreads();
    for (int off = 512; off; off >>= 1) {
        if (tid < off) sm[tid] += sm[tid + off];
        __syncthreads();
    }
    if (tid == 0) out[0] = sm[0] / (float)M;
}

// ------------------------------- launcher ----------------------------------

extern "C" void kernel_launch(void* const* d_in, const int* in_sizes, int n_in,
                              void* d_out, int out_size) {
    const float* F      = (const float*)d_in[0];
    const int*   labels = (const int*)d_in[1];
    const float* protos = (const float*)d_in[2];
    const int*   plab   = (const int*)d_in[3];
    int M = in_sizes[1];                  // 8192
    int B = in_sizes[3];                  // 100

    scan_flags_kernel<<<1, 1024>>>(labels, plab, M, B);
    convert_kernel<<<M * 16 / 256, 256>>>(F, M);
    gred_kernel<<<1, 1024>>>(M * 16 / 256 / 16);   // 512 partials

    size_t smemMain = 98304;              // 96 KB -> 2 CTAs/SM
    cudaFuncSetAttribute(mma_expsum_kernel,
                         cudaFuncAttributeMaxDynamicSharedMemorySize,
                         (int)smemMain);
    mma_expsum_kernel<<<dim3(M / 128, NCHUNK), 256, smemMain>>>(M);

    size_t smemP = (size_t)B * 129 * sizeof(float);
    cudaFuncSetAttribute(finalize_kernel,
                         cudaFuncAttributeMaxDynamicSharedMemorySize,
                         (int)smemP);
    finalize_kernel<<<M / 32, 1024, smemP>>>(F, protos, labels, M, B);

    reduce_kernel<<<1, 1024>>>((float*)d_out, M);
}

// round 8
// speedup vs baseline: 1.9323x; 1.2517x over previous
#include <cuda_runtime.h>
#include <cuda_bf16.h>
#include <math.h>
#include <stdint.h>

// ---------------------------------------------------------------------------
// SupConLossWithPrototype via mma.sync bf16, MUFU exp epilogue.
//   E[i] = sum_{j novel} exp(f_i . f_j / T).
//   Parallel flags + fused convert/compact/g-partials; 2 CTAs/SM main GEMM.
// ---------------------------------------------------------------------------

#define MAXM 8192
#define NCHUNK 9
#define LOG2E5 7.2134752044448170f

__device__ __align__(16) __nv_bfloat16 d_Ahi[(size_t)MAXM * 128];
__device__ __align__(16) __nv_bfloat16 d_Bhi[(size_t)(MAXM + 128) * 128];
__device__ int   d_flag[MAXM];
__device__ int   d_cnt[64];              // per-256-row novel counts
__device__ int   d_Nn;
__device__ float d_gpart[32 * 128];
__device__ float d_g[128];
__device__ float d_Epart[(size_t)NCHUNK * MAXM];
__device__ float d_rowloss[MAXM];

// ------------------------------ helpers ------------------------------------

__device__ __forceinline__ uint32_t s2u(const void* p) {
    uint32_t a;
    asm("{ .reg .u64 t; cvta.to.shared.u64 t, %1; cvt.u32.u64 %0, t; }"
        : "=r"(a) : "l"(p));
    return a;
}

__device__ __forceinline__ void cp16(uint32_t s, const void* g) {
    asm volatile("cp.async.cg.shared.global [%0], [%1], 16;" :: "r"(s), "l"(g));
}
#define CP_COMMIT() asm volatile("cp.async.commit_group;" ::: "memory")

__device__ __forceinline__ void ldsm4(uint32_t (&r)[4], uint32_t addr) {
    asm volatile("ldmatrix.sync.aligned.m8n8.x4.shared.b16 {%0,%1,%2,%3}, [%4];"
                 : "=r"(r[0]), "=r"(r[1]), "=r"(r[2]), "=r"(r[3]) : "r"(addr));
}

__device__ __forceinline__ void mma16816(float (&d)[4], const uint32_t (&a)[4],
                                         uint32_t b0, uint32_t b1) {
    asm volatile(
        "mma.sync.aligned.m16n8k16.row.col.f32.bf16.bf16.f32 "
        "{%0,%1,%2,%3}, {%4,%5,%6,%7}, {%8,%9}, {%0,%1,%2,%3};"
        : "+f"(d[0]), "+f"(d[1]), "+f"(d[2]), "+f"(d[3])
        : "r"(a[0]), "r"(a[1]), "r"(a[2]), "r"(a[3]), "r"(b0), "r"(b1));
}

// XOR-swizzled smem tile: 128 rows x 256B row (16 x 16B chunks).
__device__ __forceinline__ uint32_t swz(uint32_t base, int row, int kchunk) {
    return base + row * 256 + (((uint32_t)(kchunk ^ (row & 7))) << 4);
}

__device__ __forceinline__ float ex2f(float t) {
    float r;
    asm("ex2.approx.f32 %0, %1;" : "=f"(r) : "f"(t));
    return r;
}

// exp on the FMA pipe (finalize only), rel err ~1.5e-7.
__device__ __forceinline__ float fexp(float x) {
    float t = x * 1.4426950408889634f;
    float z = t + 12582912.0f;
    int   ki = __float_as_int(z) - 0x4B400000;
    float r = t - (z - 12582912.0f);
    float p =      1.5403530393381610e-4f;
    p = fmaf(p, r, 1.3333558146428443e-3f);
    p = fmaf(p, r, 9.6181291076284772e-3f);
    p = fmaf(p, r, 5.5504108664821580e-2f);
    p = fmaf(p, r, 2.4022650695910072e-1f);
    p = fmaf(p, r, 6.9314718055994531e-1f);
    p = fmaf(p, r, 1.0f);
    return __int_as_float(__float_as_int(p) + (ki << 23));
}

// --------------------------- setup kernels --------------------------------

// Parallel flags + per-block(256 rows) novel counts.
__global__ void flags_kernel(const int* __restrict__ labels,
                             const int* __restrict__ plab, int B) {
    __shared__ int sPL[128];
    __shared__ int sW[8];
    int tid = threadIdx.x, lane = tid & 31, w = tid >> 5;
    if (tid < B) sPL[tid] = plab[tid];
    __syncthreads();
    int i = blockIdx.x * 256 + tid;
    int lab = labels[i];
    int hit = 0;
    #pragma unroll 4
    for (int b = 0; b < B; ++b) hit |= (lab == sPL[b]);
    int f = hit ^ 1;
    d_flag[i] = f;
    unsigned bal = __ballot_sync(0xffffffffu, f);
    if (lane == 0) sW[w] = __popc(bal);
    __syncthreads();
    if (tid == 0) {
        int s = 0;
        #pragma unroll
        for (int q = 0; q < 8; ++q) s += sW[q];
        d_cnt[blockIdx.x] = s;
    }
}

// Fused: bf16 convert + novel compaction + g partials. 32 blocks x 256 rows.
__global__ void convert_kernel(const float* __restrict__ F, int M) {
    __shared__ int sPos[256];
    __shared__ int sW[8];
    __shared__ int sBase;
    __shared__ float sg[16][128];
    int tid = threadIdx.x, lane = tid & 31, w = tid >> 5;
    int r0 = blockIdx.x * 256;

    int fl = d_flag[r0 + tid];
    unsigned bal = __ballot_sync(0xffffffffu, fl);
    int lanePre = __popc(bal & ((1u << lane) - 1u));
    if (lane == 0) sW[w] = __popc(bal);
    if (w == 0) {                       // base = sum of preceding block counts
        int v = (lane < blockIdx.x) ? d_cnt[lane] : 0;
        #pragma unroll
        for (int off = 16; off; off >>= 1)
            v += __shfl_xor_sync(0xffffffffu, v, off);
        if (lane == 0) sBase = v;
    }
    __syncthreads();
    if (tid == 0) {
        int run = sBase;
        #pragma unroll
        for (int q = 0; q < 8; ++q) { int t = sW[q]; sW[q] = run; run += t; }
    }
    __syncthreads();
    sPos[tid] = fl ? (sW[w] + lanePre) : -1;
    __syncthreads();

    int kc = tid & 15;
    float gacc[8];
    #pragma unroll
    for (int q = 0; q < 8; ++q) gacc[q] = 0.f;

    #pragma unroll 4
    for (int sub = 0; sub < 16; ++sub) {
        int rl = sub * 16 + (tid >> 4);
        int row = r0 + rl;
        float4 v0 = *(const float4*)(F + (size_t)row * 128 + kc * 8);
        float4 v1 = *(const float4*)(F + (size_t)row * 128 + kc * 8 + 4);
        float av[8] = {v0.x, v0.y, v0.z, v0.w, v1.x, v1.y, v1.z, v1.w};
        union { __nv_bfloat16 h[8]; uint4 u; } ph;
        #pragma unroll
        for (int q = 0; q < 8; ++q) ph.h[q] = __float2bfloat16(av[q]);
        ((uint4*)d_Ahi)[(size_t)row * 16 + kc] = ph.u;
        int p = sPos[rl];
        if (p >= 0) {
            ((uint4*)d_Bhi)[(size_t)p * 16 + kc] = ph.u;
            #pragma unroll
            for (int q = 0; q < 8; ++q) gacc[q] += av[q];
        }
    }
    #pragma unroll
    for (int q = 0; q < 8; ++q) sg[tid >> 4][kc * 8 + q] = gacc[q];
    __syncthreads();
    if (tid < 128) {
        float s = 0.f;
        #pragma unroll
        for (int q = 0; q < 16; ++q) s += sg[q][tid];
        d_gpart[blockIdx.x * 128 + tid] = s;
    }
}

// g reduce (32 partials) + compute Nn + zero-pad last B tile rows.
__global__ void gred_kernel(int nblk) {        // block = 1024
    __shared__ float sm[1024];
    __shared__ int sNn;
    int t = threadIdx.x, lane = t & 31;
    if (t < 32) {
        int v = (lane < nblk) ? d_cnt[lane] : 0;
        #pragma unroll
        for (int off = 16; off; off >>= 1)
            v += __shfl_xor_sync(0xffffffffu, v, off);
        if (lane == 0) { sNn = v; d_Nn = v; }
    }
    int k = t & 127, p = t >> 7;
    float s = 0.f;
    for (int b = p; b < nblk; b += 8) s += d_gpart[b * 128 + k];
    sm[t] = s;
    __syncthreads();
    if (p == 0) {
        float tot = sm[k];
        #pragma unroll
        for (int q = 1; q < 8; ++q) tot += sm[q * 128 + k];
        d_g[k] = tot;
    }
    int Nn = sNn;
    int Npad = (Nn + 127) & ~127;
    for (int idx = t; idx < (Npad - Nn) * 16; idx += 1024) {
        int row = Nn + (idx >> 4), kc = idx & 15;
        ((uint4*)d_Bhi)[(size_t)row * 16 + kc] = make_uint4(0, 0, 0, 0);
    }
}

// ---------------------- main mma.sync exp-sum kernel -----------------------
// CTA: 128 rows x stream of 128-col novel tiles (stride NCHUNK).
// smem: A resident (32KB) + B double buffer (64KB) = 96KB; 2 CTAs/SM.
// 8 warps in 2x4 grid, warp tile 64x32, bf16 mma; register epilogue (ex2)
// runs BEFORE the barrier so it hides in barrier skew.

__global__ __launch_bounds__(256, 2) void mma_expsum_kernel(int M) {
    extern __shared__ char dyn[];
    const uint32_t sbase = s2u(dyn);
    const uint32_t sA = sbase;
    const uint32_t sB[2] = {sbase + 32768, sbase + 65536};

    int tid = threadIdx.x;
    int lane = tid & 31, w = tid >> 5;
    int wr = w >> 2, wc = w & 3;               // warp grid 2 x 4
    int rowbase = blockIdx.x * 128;
    int chunk = blockIdx.y;
    int Nn = d_Nn;
    int ntiles = (Nn + 127) >> 7;
    int nt = (ntiles > chunk) ? ((ntiles - chunk + NCHUNK - 1) / NCHUNK) : 0;

    // Prologue: A (group 0, with B0) + B1 (group 1).
    {
        const char* ga = (const char*)d_Ahi + (size_t)blockIdx.x * 32768;
        #pragma unroll
        for (int it = 0; it < 8; ++it) {
            int c = it * 256 + tid;
            cp16(swz(sA, c >> 4, c & 15), ga + (size_t)c * 16);
        }
        if (nt > 0) {
            const char* gb = (const char*)d_Bhi + (size_t)chunk * 32768;
            #pragma unroll
            for (int it = 0; it < 8; ++it) {
                int c = it * 256 + tid;
                cp16(swz(sB[0], c >> 4, c & 15), gb + (size_t)c * 16);
            }
        }
        CP_COMMIT();
        if (nt > 1) {
            const char* gb = (const char*)d_Bhi + (size_t)(chunk + NCHUNK) * 32768;
            #pragma unroll
            for (int it = 0; it < 8; ++it) {
                int c = it * 256 + tid;
                cp16(swz(sB[1], c >> 4, c & 15), gb + (size_t)c * 16);
            }
            CP_COMMIT();
        }
    }

    int rl = lane & 15;                 // ldmatrix row within 16-row group
    int khalf = lane >> 4;              // +1 k-chunk for upper half
    float rs[8];
    #pragma unroll
    for (int q = 0; q < 8; ++q) rs[q] = 0.f;

    for (int k = 0; k < nt; ++k) {
        int p = k & 1;
        if (k + 1 < nt) asm volatile("cp.async.wait_group 1;" ::: "memory");
        else            asm volatile("cp.async.wait_group 0;" ::: "memory");
        __syncthreads();

        float acc[4][4][4];
        #pragma unroll
        for (int mi = 0; mi < 4; ++mi)
            #pragma unroll
            for (int ni = 0; ni < 4; ++ni)
                #pragma unroll
                for (int q = 0; q < 4; ++q) acc[mi][ni][q] = 0.f;

        #pragma unroll
        for (int ks = 0; ks < 8; ++ks) {
            int kc = ks * 2 + khalf;
            uint32_t a[4][4], b[2][4];
            #pragma unroll
            for (int mi = 0; mi < 4; ++mi)
                ldsm4(a[mi], swz(sA, wr * 64 + mi * 16 + rl, kc));
            #pragma unroll
            for (int n2 = 0; n2 < 2; ++n2)
                ldsm4(b[n2], swz(sB[p], wc * 32 + n2 * 16 + rl, kc));
            #pragma unroll
            for (int mi = 0; mi < 4; ++mi)
                #pragma unroll
                for (int ni = 0; ni < 4; ++ni) {
                    int n2 = ni >> 1, pr = ni & 1;
                    mma16816(acc[mi][ni], a[mi], b[n2][pr], b[n2][pr + 2]);
                }
        }

        // Register-only exp epilogue BEFORE the barrier (hides in skew).
        int cwarp = (chunk + k * NCHUNK) * 128 + wc * 32;
        if (cwarp + 32 <= Nn) {
            #pragma unroll
            for (int mi = 0; mi < 4; ++mi)
                #pragma unroll
                for (int ni = 0; ni < 4; ++ni) {
                    rs[mi * 2 + 0] += ex2f(acc[mi][ni][0] * LOG2E5) +
                                      ex2f(acc[mi][ni][1] * LOG2E5);
                    rs[mi * 2 + 1] += ex2f(acc[mi][ni][2] * LOG2E5) +
                                      ex2f(acc[mi][ni][3] * LOG2E5);
                }
        } else {
            #pragma unroll
            for (int mi = 0; mi < 4; ++mi)
                #pragma unroll
                for (int ni = 0; ni < 4; ++ni) {
                    int c0 = cwarp + ni * 8 + (lane & 3) * 2;
                    float t0 = (c0     < Nn) ? acc[mi][ni][0] * LOG2E5 : -1e30f;
                    float t1 = (c0 + 1 < Nn) ? acc[mi][ni][1] * LOG2E5 : -1e30f;
                    float t2 = (c0     < Nn) ? acc[mi][ni][2] * LOG2E5 : -1e30f;
                    float t3 = (c0 + 1 < Nn) ? acc[mi][ni][3] * LOG2E5 : -1e30f;
                    rs[mi * 2 + 0] += ex2f(t0) + ex2f(t1);
                    rs[mi * 2 + 1] += ex2f(t2) + ex2f(t3);
                }
        }

        __syncthreads();

        if (k + 2 < nt) {                   // prefetch B(k+2) into buffer p
            const char* gb = (const char*)d_Bhi +
                             (size_t)(chunk + (k + 2) * NCHUNK) * 32768;
            #pragma unroll
            for (int it = 0; it < 8; ++it) {
                int c = it * 256 + tid;
                cp16(swz(sB[p], c >> 4, c & 15), gb + (size_t)c * 16);
            }
            CP_COMMIT();
        }
    }

    // Quad reduce (lanes sharing a row), then cross-warp-col reduce in smem.
    #pragma unroll
    for (int q = 0; q < 8; ++q) {
        rs[q] += __shfl_xor_sync(0xffffffffu, rs[q], 1);
        rs[q] += __shfl_xor_sync(0xffffffffu, rs[q], 2);
    }
    __syncthreads();
    float* sred = (float*)dyn;              // 128 rows x 4 warp-cols
    if ((lane & 3) == 0) {
        int g = lane >> 2;
        #pragma unroll
        for (int mi = 0; mi < 4; ++mi)
            #pragma unroll
            for (int r8 = 0; r8 < 2; ++r8) {
                int row = wr * 64 + mi * 16 + r8 * 8 + g;
                sred[row * 4 + wc] = rs[mi * 2 + r8];
            }
    }
    __syncthreads();
    if (tid < 128) {
        float s = sred[tid * 4] + sred[tid * 4 + 1] +
                  sred[tid * 4 + 2] + sred[tid * 4 + 3];
        d_Epart[(size_t)chunk * M + rowbase + tid] = s;
    }
}

// --------------------------- finalize + reduce -----------------------------
// 1024 threads, 32 rows per block.

__global__ void finalize_kernel(const float* __restrict__ F,
                                const float* __restrict__ protos,
                                const int* __restrict__ labels,
                                int M, int B) {
    extern __shared__ float sP[];          // B*129 floats
    __shared__ float fR[32][128];
    int tid = threadIdx.x, lane = tid & 31, w = tid >> 5;

    for (int idx = tid; idx < B * 128; idx += 1024) {
        int b = idx >> 7, k = idx & 127;
        sP[b * 129 + k] = protos[idx];
    }
    int i = blockIdx.x * 32 + w;
    {
        float4 v = *(const float4*)(F + (size_t)i * 128 + lane * 4);
        *(float4*)&fR[w][lane * 4] = v;
    }
    __syncthreads();

    float dg = 0.f, ds = 0.f;
    #pragma unroll
    for (int q = 0; q < 4; ++q) {
        float fv = fR[w][lane * 4 + q];
        dg = fmaf(fv, d_g[lane * 4 + q], dg);
        ds = fmaf(fv, fv, ds);
    }

    float psum = 0.f, pexp = 0.f, bipi = 0.f;
    int lab = labels[i];
    #pragma unroll
    for (int pb = 0; pb < 4; ++pb) {
        int b = lane + pb * 32;
        if (b < B) {
            float d = 0.f;
            #pragma unroll 8
            for (int k = 0; k < 128; ++k)
                d = fmaf(fR[w][k], sP[b * 129 + k], d);
            float P = d * 5.0f;
            psum += P;
            pexp += fexp(P);
            if (b == lab) bipi = P;
        }
    }
    #pragma unroll
    for (int off = 16; off; off >>= 1) {
        dg   += __shfl_xor_sync(0xffffffffu, dg, off);
        ds   += __shfl_xor_sync(0xffffffffu, ds, off);
        psum += __shfl_xor_sync(0xffffffffu, psum, off);
        pexp += __shfl_xor_sync(0xffffffffu, pexp, off);
        bipi += __shfl_xor_sync(0xffffffffu, bipi, off);
    }

    if (lane == 0) {
        float E = 0.f;
        #pragma unroll
        for (int c = 0; c < NCHUNK; ++c) E += d_Epart[(size_t)c * M + i];
        float loss;
        if (d_flag[i]) {
            float Sii = ds * 5.0f;
            float den = (E - fexp(Sii)) + psum;
            int cnt = d_Nn - 1;
            if (cnt > 0) {
                float sumS = dg * 5.0f - Sii;
                loss = -((sumS - logf(den) * (float)cnt) / (float)cnt);
            } else {
                loss = 0.f;
            }
        } else {
            loss = -(bipi - logf(E + pexp));
        }
        d_rowloss[i] = loss;
    }
}

__global__ void reduce_kernel(float* __restrict__ out, int M) {
    __shared__ float sm[1024];
    int tid = threadIdx.x;
    float s = 0.f;
    for (int i = tid; i < M; i += 1024) s += d_rowloss[i];
    sm[tid] = s;
    __syncthreads();
    for (int off = 512; off; off >>= 1) {
        if (tid < off) sm[tid] += sm[tid + off];
        __syncthreads();
    }
    if (tid == 0) out[0] = sm[0] / (float)M;
}

// ------------------------------- launcher ----------------------------------

extern "C" void kernel_launch(void* const* d_in, const int* in_sizes, int n_in,
                              void* d_out, int out_size) {
    const float* F      = (const float*)d_in[0];
    const int*   labels = (const int*)d_in[1];
    const float* protos = (const float*)d_in[2];
    const int*   plab   = (const int*)d_in[3];
    int M = in_sizes[1];                  // 8192
    int B = in_sizes[3];                  // 100
    int nblk = M / 256;                   // 32

    flags_kernel<<<nblk, 256>>>(labels, plab, B);
    convert_kernel<<<nblk, 256>>>(F, M);
    gred_kernel<<<1, 1024>>>(nblk);

    size_t smemMain = 98304;              // 96 KB -> 2 CTAs/SM
    cudaFuncSetAttribute(mma_expsum_kernel,
                         cudaFuncAttributeMaxDynamicSharedMemorySize,
                         (int)smemMain);
    mma_expsum_kernel<<<dim3(M / 128, NCHUNK), 256, smemMain>>>(M);

    size_t smemP = (size_t)B * 129 * sizeof(float);
    cudaFuncSetAttribute(finalize_kernel,
                         cudaFuncAttributeMaxDynamicSharedMemorySize,
                         (int)smemP);
    finalize_kernel<<<M / 32, 1024, smemP>>>(F, protos, labels, M, B);

    reduce_kernel<<<1, 1024>>>((float*)d_out, M);
}